// round 16
// baseline (speedup 1.0000x reference)
#include <cuda_runtime.h>
#include <cuda_bf16.h>
#include <cstdint>

// Problem constants
#define SD      16384        // S*D
#define NJ      22           // 14 alpha cols + 8 beta cols
#define NJP     24           // padded (2 zero cols)
#define BN      2048         // B*N
#define KC      8            // k-chunks (2048 floats each, == s)
#define MT      16           // m-tiles of 128 bn
#define NTILE   32           // 64-k tiles per chunk
#define KT_TOT  256          // total 64-k tiles (SD/64)

typedef unsigned long long ull;

// g_Wf: B operand pre-baked in mma.m16n8k16 B-fragment layout (R8 layout).
// [kt][ks 0..3][ng 0..2][lane 0..31] -> uint2 {b0, b1}:
//   j = ng*8 + lane/4,  k0 = kt*64 + ks*16 + (lane%4)*2
//   b0 = bf16x2( w[j][k0],   w[j][k0+1] )
//   b1 = bf16x2( w[j][k0+8], w[j][k0+9] )
// with w[j][k] = (gamma[k]+1) * W[k][j], j>=22 -> 0.
__device__ __align__(16) uint2 g_Wf[KT_TOT * 12 * 32];
__device__ float g_part[KC][BN][NJP];
__device__ float g_ss[KC][BN];

__device__ __forceinline__ uint32_t pack_bf16x2(float lo, float hi) {
    __nv_bfloat162 h = __float22bfloat162_rn(make_float2(lo, hi));
    return *reinterpret_cast<uint32_t*>(&h);
}

__device__ __forceinline__ void mma_bf16(float* d, const uint32_t* a, uint2 b) {
    asm volatile(
        "mma.sync.aligned.m16n8k16.row.col.f32.bf16.bf16.f32 "
        "{%0,%1,%2,%3}, {%4,%5,%6,%7}, {%8,%9}, {%0,%1,%2,%3};"
        : "+f"(d[0]), "+f"(d[1]), "+f"(d[2]), "+f"(d[3])
        : "r"(a[0]), "r"(a[1]), "r"(a[2]), "r"(a[3]), "r"(b.x), "r"(b.y));
}

// ---------------------------------------------------------------------------
// Kernel P: bake B fragments, fully coalesced. One CTA per kt (64-k tile):
// stage gamma (64), Wa row-block (896 = 64x14, contiguous) and Wb row-block
// (512 = 64x8, contiguous) into smem with perfectly coalesced LDGs, then
// emit the 384 packed uint2 fragments from smem. Same output as R8's prepW.
// ---------------------------------------------------------------------------
__global__ __launch_bounds__(256) void k_prepW(const float* __restrict__ gamma,
                                               const float* __restrict__ Wa,
                                               const float* __restrict__ Wb) {
    __shared__ float gS[64];
    __shared__ float wS[NJP][64];        // wS[j][k_local], rows 22-23 zero
    const int kt  = blockIdx.x;
    const int tid = threadIdx.x;
    const int kbase = kt * 64;

    if (tid < 64) gS[tid] = gamma[kbase + tid] + 1.0f;
    if (tid >= 64 && tid < 192)          // zero the 2 padding rows (128 floats)
        (&wS[0][0])[22 * 64 + (tid - 64)] = 0.0f;
    __syncthreads();

    // Wa block: rows kbase..kbase+63 span floats [kbase*14, kbase*14+896)
    #pragma unroll
    for (int i = tid; i < 896; i += 256) {
        int k = i / 14, j = i - k * 14;
        wS[j][k] = gS[k] * Wa[(size_t)kbase * 14 + i];
    }
    // Wb block: contiguous 512 floats
    #pragma unroll
    for (int i = tid; i < 512; i += 256) {
        int k = i >> 3, j = i & 7;
        wS[14 + j][k] = gS[k] * Wb[(size_t)kbase * 8 + i];
    }
    __syncthreads();

    // emit fragments: idx = f*32 + lane, f = ks*3 + ng
    #pragma unroll
    for (int idx = tid; idx < 384; idx += 256) {
        int f = idx >> 5, lane = idx & 31;
        int ks = f / 3, ng = f - ks * 3;
        int quad = lane >> 2, pos = lane & 3;
        int j  = ng * 8 + quad;
        int k0 = ks * 16 + pos * 2;
        uint2 o;
        o.x = pack_bf16x2(wS[j][k0],     wS[j][k0 + 1]);
        o.y = pack_bf16x2(wS[j][k0 + 8], wS[j][k0 + 9]);
        g_Wf[(size_t)kt * 384 + idx] = o;
    }
}

// ---------------------------------------------------------------------------
// Kernel A: tensor-core reductions via warp-level bf16 mma.sync.
// (identical to the R8 best: grid=(MT,KC)=128 CTAs, 256 threads, warp owns
// 16 bn rows x 2048 k, no smem, no syncs)
// ---------------------------------------------------------------------------
__global__ __launch_bounds__(256, 1) void k_reduce(const float* __restrict__ resid) {
    const int warp = threadIdx.x >> 5;
    const int lane = threadIdx.x & 31;
    const int quad = lane >> 2, pos = lane & 3;
    const int mt = blockIdx.x, chunk = blockIdx.y;
    const int b = mt >> 3, nbase = (mt & 7) * 128;

    const int row_lo = warp * 16 + quad;       // fragment rows quad / quad+8
    const float2* r2 = reinterpret_cast<const float2*>(resid);
    const size_t off_lo = (size_t)b * 8388608u + (size_t)chunk * 1048576u
                        + (size_t)(nbase + row_lo) * 1024u;
    const size_t off_hi = off_lo + 8u * 1024u;

    float acc[3][4];
    #pragma unroll
    for (int ng = 0; ng < 3; ng++)
        #pragma unroll
        for (int e = 0; e < 4; e++) acc[ng][e] = 0.0f;
    float ss_lo = 0.0f, ss_hi = 0.0f;

    #pragma unroll 1
    for (int t = 0; t < NTILE; t++) {
        // A loads: 16 float2, all independent (MLP=16)
        float2 av[4][4];
        const int kb2 = t * 32 + pos;          // float2 index of k = t*64+pos*2
        #pragma unroll
        for (int ks = 0; ks < 4; ks++) {
            const int c0 = kb2 + ks * 8;
            av[ks][0] = r2[off_lo + c0];
            av[ks][1] = r2[off_hi + c0];
            av[ks][2] = r2[off_lo + c0 + 4];   // k+8
            av[ks][3] = r2[off_hi + c0 + 4];
        }
        // B fragments: 12 coalesced uint2 (L1/L2-resident, shared by all warps)
        uint2 bv[12];
        const uint2* wt = g_Wf + (size_t)(chunk * NTILE + t) * 384 + lane;
        #pragma unroll
        for (int i = 0; i < 12; i++) bv[i] = wt[i * 32];

        #pragma unroll
        for (int ks = 0; ks < 4; ks++) {
            // fp32 sumsq from the same registers
            ss_lo = fmaf(av[ks][0].x, av[ks][0].x, ss_lo);
            ss_lo = fmaf(av[ks][0].y, av[ks][0].y, ss_lo);
            ss_lo = fmaf(av[ks][2].x, av[ks][2].x, ss_lo);
            ss_lo = fmaf(av[ks][2].y, av[ks][2].y, ss_lo);
            ss_hi = fmaf(av[ks][1].x, av[ks][1].x, ss_hi);
            ss_hi = fmaf(av[ks][1].y, av[ks][1].y, ss_hi);
            ss_hi = fmaf(av[ks][3].x, av[ks][3].x, ss_hi);
            ss_hi = fmaf(av[ks][3].y, av[ks][3].y, ss_hi);
            // cvt -> bf16 A fragment
            uint32_t a[4];
            a[0] = pack_bf16x2(av[ks][0].x, av[ks][0].y);
            a[1] = pack_bf16x2(av[ks][1].x, av[ks][1].y);
            a[2] = pack_bf16x2(av[ks][2].x, av[ks][2].y);
            a[3] = pack_bf16x2(av[ks][3].x, av[ks][3].y);
            #pragma unroll
            for (int ng = 0; ng < 3; ng++)
                mma_bf16(acc[ng], a, bv[ks * 3 + ng]);
        }
    }

    // store dot partials: D frag (m16n8): c0,c1 -> row quad, cols pos*2,+1
    const int bn_lo = mt * 128 + row_lo;
    #pragma unroll
    for (int ng = 0; ng < 3; ng++) {
        const int j0 = ng * 8 + pos * 2;
        *reinterpret_cast<float2*>(&g_part[chunk][bn_lo][j0]) =
            make_float2(acc[ng][0], acc[ng][1]);
        *reinterpret_cast<float2*>(&g_part[chunk][bn_lo + 8][j0]) =
            make_float2(acc[ng][2], acc[ng][3]);
    }
    // sumsq: reduce across the 4 lanes sharing this quad
    #pragma unroll
    for (int o = 1; o < 4; o <<= 1) {
        ss_lo += __shfl_xor_sync(0xffffffffu, ss_lo, o, 4);
        ss_hi += __shfl_xor_sync(0xffffffffu, ss_hi, o, 4);
    }
    if (pos == 0) {
        g_ss[chunk][bn_lo]     = ss_lo;
        g_ss[chunk][bn_lo + 8] = ss_hi;
    }
}

// ---------------------------------------------------------------------------
// Kernel C (fused): prologue rebuilds this bn's 8x8 mixing matrix M from the
// partials (k_mix inlined, fixed-order sums -> deterministic), then the
// unchanged R8 apply body: out[t,d] = sum_s M[s][t] * r[s,d]. grid=(BN, 2).
// ---------------------------------------------------------------------------
__global__ __launch_bounds__(256) void k_apply(const float* __restrict__ resid,
                                               float* __restrict__ out,
                                               const float* __restrict__ salpha,
                                               const float* __restrict__ pbs,
                                               const float* __restrict__ rscale,
                                               const float* __restrict__ sbeta,
                                               const float* __restrict__ hps) {
    const int bn = blockIdx.x;
    const int b = bn >> 10, n = bn & 1023;
    const int tid = threadIdx.x;

    __shared__ float pS[8][24];
    __shared__ float dotS[23];
    __shared__ float wpreS[8], betaS[8], pk3[3];
    __shared__ float Ms[64];

    // gather partials: 192 threads, one (chunk, j) each
    if (tid < 192) {
        int c = tid / 24, j = tid - c * 24;
        float v = 0.0f;
        if (j < 22)       v = g_part[c][bn][j];
        else if (j == 22) v = g_ss[c][bn];
        pS[c][j] = v;
    }
    __syncthreads();
    // fixed-order chunk sums (deterministic)
    if (tid < 23) {
        float v = 0.0f;
        #pragma unroll
        for (int c = 0; c < KC; c++) v += pS[c][tid];
        dotS[tid] = v;
    }
    __syncthreads();
    // scalar stage (split across threads 0..18)
    if (tid < 19) {
        float scale = rsqrtf(fmaxf(dotS[22], 1e-24f)) * 128.0f;  // sqrt(16384)
        if (tid < 8) {
            // wpre[tid] = softmax(ps * dyn_pre + static_alpha[:8])[tid]
            float ps = pbs[0];
            float l[8], mx = -1e30f;
            #pragma unroll
            for (int i = 0; i < 8; i++) {
                l[i] = ps * (scale * dotS[i]) + salpha[i];
                mx = fmaxf(mx, l[i]);
            }
            float sum = 0.0f;
            #pragma unroll
            for (int i = 0; i < 8; i++) sum += expf(l[i] - mx);
            wpreS[tid] = expf(l[tid] - mx) / sum;
        } else if (tid < 16) {
            int t = tid - 8;
            float hp = hps[0];
            betaS[t] = 1.0f / (1.0f + expf(-(hp * (scale * dotS[14 + t]) + sbeta[t])));
        } else {
            int k = tid - 16;
            float rs = rscale[0];
            float c0 = rs * (scale * dotS[8 + 2 * k])     + salpha[8 + 2 * k];
            float c1 = rs * (scale * dotS[8 + 2 * k + 1]) + salpha[8 + 2 * k + 1];
            pk3[k] = 1.0f / (1.0f + expf(c1 - c0));
        }
    }
    __syncthreads();
    // M[s][t] = h[s^t] + beta[t]*wpre[s]
    if (tid < 64) {
        int s = tid >> 3, t = tid & 7, x = s ^ t;
        float f0 = (x & 4) ? (1.0f - pk3[0]) : pk3[0];
        float f1 = (x & 2) ? (1.0f - pk3[1]) : pk3[1];
        float f2 = (x & 1) ? (1.0f - pk3[2]) : pk3[2];
        Ms[tid] = f0 * f1 * f2 + betaS[t] * wpreS[s];
    }
    __syncthreads();

    // ---- unchanged R8 apply body ----
    float M[64];
    #pragma unroll
    for (int i = 0; i < 64; i++) M[i] = Ms[i];

    const size_t base = (size_t)b * 16777216u + (size_t)n * 2048u;
    const int d = blockIdx.y * 1024 + tid * 4;

    float4 acc[8];
    #pragma unroll
    for (int t = 0; t < 8; t++) acc[t] = make_float4(0.f, 0.f, 0.f, 0.f);

    #pragma unroll
    for (int s = 0; s < 8; s++) {
        float4 r4 = *reinterpret_cast<const float4*>(resid + base + (size_t)s * 2097152u + d);
        #pragma unroll
        for (int t = 0; t < 8; t++) {
            float m = M[s * 8 + t];
            acc[t].x += m * r4.x;
            acc[t].y += m * r4.y;
            acc[t].z += m * r4.z;
            acc[t].w += m * r4.w;
        }
    }
    #pragma unroll
    for (int t = 0; t < 8; t++)
        *reinterpret_cast<float4*>(out + base + (size_t)t * 2097152u + d) = acc[t];
}

// ---------------------------------------------------------------------------
extern "C" void kernel_launch(void* const* d_in, const int* in_sizes, int n_in,
                              void* d_out, int out_size) {
    const float* resid  = (const float*)d_in[0];   // residuals (B*S, N, D)
    const float* gamma  = (const float*)d_in[1];   // (S*D,)
    const float* salpha = (const float*)d_in[2];   // (S+T,) = 14
    const float* Wa     = (const float*)d_in[3];   // (S*D, 14)
    const float* pbs    = (const float*)d_in[4];   // (1,)
    const float* rs     = (const float*)d_in[5];   // (1,)
    const float* sbeta  = (const float*)d_in[6];   // (S,) = 8
    const float* Wb     = (const float*)d_in[7];   // (S*D, 8)
    const float* hps    = (const float*)d_in[8];   // scalar
    float* out = (float*)d_out;

    k_prepW<<<KT_TOT, 256>>>(gamma, Wa, Wb);
    k_reduce<<<dim3(MT, KC), 256>>>(resid);
    k_apply<<<dim3(BN, 2), 256>>>(resid, out, salpha, pbs, rs, sbeta, hps);
}